// round 8
// baseline (speedup 1.0000x reference)
#include <cuda_runtime.h>
#include <math.h>
#include <float.h>
#include <stdint.h>

#define NN 256
#define CC 128
#define HH 4
#define DD 32
#define MM (NN*NN)     // 65536
#define HD (HH*DD)     // 128
#define INF_ 1e9f
#define LN_EPS 1e-5f

// ---- scratch ----
__device__ float g_q [MM*HD];       // tf32-rounded, scale applied
__device__ float g_k [MM*HD];       // tf32-rounded
__device__ float g_v [MM*HD];       // tf32-rounded
__device__ float g_g [MM*HD];       // gate pre-sigmoid (tf32-rounded)
__device__ float g_o [MM*HD];       // fp32
__device__ float g_tbt[HH*NN*NN];   // [h][j][k], fp32
__device__ float g_woT[CC*HD];      // [k][n] = wo[n][k] (tf32-rounded)

// ---------------------------------------------------------------
// tf32 helpers
// ---------------------------------------------------------------
__device__ __forceinline__ uint32_t f2tf(float x) {
    uint32_t r;
    asm("cvt.rna.tf32.f32 %0, %1;" : "=r"(r) : "f"(x));
    return r;
}
__device__ __forceinline__ float f2tf_f(float x) {
    return __uint_as_float(f2tf(x));
}

__device__ __forceinline__ void mma_tf32(float c[4], const uint32_t a[4],
                                         uint32_t b0, uint32_t b1) {
    asm volatile(
        "mma.sync.aligned.m16n8k8.row.col.f32.tf32.tf32.f32 "
        "{%0,%1,%2,%3}, {%4,%5,%6,%7}, {%8,%9}, {%0,%1,%2,%3};\n"
        : "+f"(c[0]), "+f"(c[1]), "+f"(c[2]), "+f"(c[3])
        : "r"(a[0]), "r"(a[1]), "r"(a[2]), "r"(a[3]), "r"(b0), "r"(b1));
}

// ---------------------------------------------------------------
// Kernel 1: fused LayerNorm + q/k/v/g projection (tf32 mma)
// grid (MM/128, 4). Block LNs its 128 rows into smem, then GEMMs.
// y==0 blocks also emit the triangle bias (from unrounded values).
// ---------------------------------------------------------------
#define AS2_STR 132
#define AS2_SZ (128*AS2_STR)        // 16896 floats
#define BS_STR 136
#define BS_SZ (32*BS_STR)           // 4352 floats
#define PROJF_SMEM ((AS2_SZ + 2*BS_SZ)*4)   // 102400 B

__global__ __launch_bounds__(256, 2)
void gemm_proj_fused(const float* __restrict__ x,
                     const float* __restrict__ ln_w,
                     const float* __restrict__ ln_b,
                     const float* __restrict__ w_bias,
                     const float* __restrict__ W0, const float* __restrict__ W1,
                     const float* __restrict__ W2, const float* __restrict__ W3)
{
    extern __shared__ float ps[];
    float* As = ps;                  // [128][132]
    float* Bs = ps + AS2_SZ;         // [2][32][136]

    const float* W;
    float* Out;
    float osc = 1.0f;
    switch (blockIdx.y) {
        case 0: W = W0; Out = g_q; osc = 0.17677669529663689f; break;
        case 1: W = W1; Out = g_k; break;
        case 2: W = W2; Out = g_v; break;
        default: W = W3; Out = g_g; break;
    }
    int m0 = blockIdx.x * 128;

    int tid = threadIdx.x;
    int warp = tid >> 5, lane = tid & 31;

    auto load_B = [&](int buf, int k0) {
        float* B = Bs + buf*BS_SZ;
        #pragma unroll
        for (int i = 0; i < 4; i++) {
            int f = tid + 256*i;
            int kk = f >> 5;
            int nq = (f & 31) * 4;
            float4 b = *(const float4*)&W[(k0 + kk)*HD + nq];
            b.x = f2tf_f(b.x); b.y = f2tf_f(b.y);
            b.z = f2tf_f(b.z); b.w = f2tf_f(b.w);
            *(float4*)&B[kk*BS_STR + nq] = b;
        }
    };

    load_B(0, 0);

    // ---- Phase 1: LayerNorm, warp per row, 16 rows/warp ----
    bool do_tb = (blockIdx.y == 0);
    for (int it = 0; it < 16; it++) {
        int row = warp*16 + it;
        int m = m0 + row;
        int i1 = m >> 8, i2 = m & 255;

        float4 v4 = *(const float4*)&x[(i2*NN + i1)*CC + lane*4];
        float s = v4.x + v4.y + v4.z + v4.w;
        #pragma unroll
        for (int o = 16; o > 0; o >>= 1) s += __shfl_xor_sync(0xffffffffu, s, o);
        float mu = s * (1.0f / CC);

        float dx = v4.x - mu, dy = v4.y - mu, dz = v4.z - mu, dw = v4.w - mu;
        float s2 = dx*dx + dy*dy + dz*dz + dw*dw;
        #pragma unroll
        for (int o = 16; o > 0; o >>= 1) s2 += __shfl_xor_sync(0xffffffffu, s2, o);
        float rs = rsqrtf(s2 * (1.0f / CC) + LN_EPS);

        float4 w4 = *(const float4*)&ln_w[lane*4];
        float4 b4 = *(const float4*)&ln_b[lane*4];
        float xn0 = dx*rs*w4.x + b4.x;
        float xn1 = dy*rs*w4.y + b4.y;
        float xn2 = dz*rs*w4.z + b4.z;
        float xn3 = dw*rs*w4.w + b4.w;

        *(float4*)&As[row*AS2_STR + lane*4] =
            make_float4(f2tf_f(xn0), f2tf_f(xn1), f2tf_f(xn2), f2tf_f(xn3));

        if (do_tb) {
            float acc[4];
            #pragma unroll
            for (int h = 0; h < 4; h++) {
                float4 wb = *(const float4*)&w_bias[h*CC + lane*4];
                acc[h] = xn0*wb.x + xn1*wb.y + xn2*wb.z + xn3*wb.w;
            }
            #pragma unroll
            for (int o = 16; o > 0; o >>= 1) {
                #pragma unroll
                for (int h = 0; h < 4; h++)
                    acc[h] += __shfl_xor_sync(0xffffffffu, acc[h], o);
            }
            if (lane < 4)
                g_tbt[(lane*NN + i1)*NN + i2] = acc[lane];
        }
    }
    __syncthreads();

    // ---- Phase 2: GEMM ----
    int g = lane >> 2, t = lane & 3;
    int wm = warp >> 2, wn = warp & 3;
    int mbase = wm*64, nbase = wn*32;

    float acc[4][4][4] = {};

    for (int st = 0; st < 4; st++) {
        if (st < 3) load_B((st + 1) & 1, (st + 1) * 32);
        float* B = Bs + (st & 1)*BS_SZ;
        #pragma unroll
        for (int ks = 0; ks < 4; ks++) {
            int col = st*32 + ks*8 + t;
            uint32_t af[4][4];
            #pragma unroll
            for (int mt = 0; mt < 4; mt++) {
                int r0 = mbase + mt*16 + g;
                af[mt][0] = __float_as_uint(As[ r0     *AS2_STR + col    ]);
                af[mt][1] = __float_as_uint(As[(r0 + 8)*AS2_STR + col    ]);
                af[mt][2] = __float_as_uint(As[ r0     *AS2_STR + col + 4]);
                af[mt][3] = __float_as_uint(As[(r0 + 8)*AS2_STR + col + 4]);
            }
            uint32_t bf0[4], bf1[4];
            #pragma unroll
            for (int nt = 0; nt < 4; nt++) {
                int nc = nbase + nt*8 + g;
                bf0[nt] = __float_as_uint(B[(ks*8 + t    )*BS_STR + nc]);
                bf1[nt] = __float_as_uint(B[(ks*8 + t + 4)*BS_STR + nc]);
            }
            #pragma unroll
            for (int mt = 0; mt < 4; mt++)
                #pragma unroll
                for (int nt = 0; nt < 4; nt++)
                    mma_tf32(acc[mt][nt], af[mt], bf0[nt], bf1[nt]);
        }
        __syncthreads();
    }

    #pragma unroll
    for (int mt = 0; mt < 4; mt++) {
        int row0 = m0 + mbase + mt*16 + g;
        int row1 = row0 + 8;
        #pragma unroll
        for (int nt = 0; nt < 4; nt++) {
            int col = nbase + nt*8 + 2*t;
            float2 w0 = make_float2(f2tf_f(acc[mt][nt][0]*osc), f2tf_f(acc[mt][nt][1]*osc));
            float2 w1 = make_float2(f2tf_f(acc[mt][nt][2]*osc), f2tf_f(acc[mt][nt][3]*osc));
            *(float2*)&Out[row0*HD + col] = w0;
            *(float2*)&Out[row1*HD + col] = w1;
        }
    }
}

// ---------------------------------------------------------------
// Kernel 2: wo transpose
// ---------------------------------------------------------------
__global__ void transpose_wo(const float* __restrict__ wo)
{
    int idx = blockIdx.x * 256 + threadIdx.x;
    int n = idx >> 7, k = idx & 127;
    g_woT[k*HD + n] = f2tf_f(wo[n*HD + k]);
}

// ---------------------------------------------------------------
// Kernel 3: tf32 mma flash attention, 8 warps x 32 queries,
// no-max softmax (scores bounded; masked -> exp underflows to 0),
// thread-local row-sum accumulation (no per-chunk shuffles).
// ---------------------------------------------------------------
#define KS_STR 36
#define VS_STR 40
#define ATTN_SMEM ((NN*KS_STR + NN*VS_STR + NN) * 4)

__global__ __launch_bounds__(256)
void attn_mma(const float* __restrict__ mask)
{
    extern __shared__ float sm[];
    float* Ks = sm;                         // [256][36]
    float* Vs = sm + NN*KS_STR;             // [256][40]
    float* mb = sm + NN*KS_STR + NN*VS_STR; // [256]

    int I = blockIdx.x, h = blockIdx.y;
    int tid  = threadIdx.x;
    int warp = tid >> 5, lane = tid & 31;
    int g = lane >> 2, t = lane & 3;

    const float* kbase = g_k + (size_t)(I*NN)*HD + h*DD;
    const float* vbase = g_v + (size_t)(I*NN)*HD + h*DD;
    #pragma unroll
    for (int p = 0; p < 8; p++) {
        int slot = p*256 + tid;             // 0..2047
        int key = slot >> 3;
        int d4  = (slot & 7) * 4;
        *(float4*)&Ks[key*KS_STR + d4] = *(const float4*)&kbase[key*HD + d4];
        *(float4*)&Vs[key*VS_STR + d4] = *(const float4*)&vbase[key*HD + d4];
    }
    mb[tid] = INF_ * (mask[tid*NN + I] - 1.0f);

    int q0 = warp * 32;
    const float* qbase = g_q + (size_t)(I*NN)*HD + h*DD;
    uint32_t aq[2][4][4];
    #pragma unroll
    for (int mt = 0; mt < 2; mt++)
        #pragma unroll
        for (int ks = 0; ks < 4; ks++)
            #pragma unroll
            for (int r = 0; r < 4; r++) {
                int row = q0 + mt*16 + (r & 1)*8 + g;
                int col = ks*8 + t + (r >> 1)*4;
                aq[mt][ks][r] = __float_as_uint(qbase[row*HD + col]);
            }

    float Of[2][4][4] = {};
    float lacc[2][2] = {};

    const float* tbp = g_tbt + h*NN*NN;     // [j][k]

    __syncthreads();

    for (int kc = 0; kc < NN; kc += 64) {
        // ---- S = Q K^T ----
        float S[2][8][4] = {};
        #pragma unroll
        for (int nt = 0; nt < 8; nt++) {
            int n0 = kc + nt*8;
            #pragma unroll
            for (int ks = 0; ks < 4; ks++) {
                uint32_t b0 = __float_as_uint(Ks[(n0 + g)*KS_STR + ks*8 + t]);
                uint32_t b1 = __float_as_uint(Ks[(n0 + g)*KS_STR + ks*8 + t + 4]);
                mma_tf32(S[0][nt], aq[0][ks], b0, b1);
                mma_tf32(S[1][nt], aq[1][ks], b0, b1);
            }
        }
        // ---- biases + exp + row-sum accumulation ----
        #pragma unroll
        for (int nt = 0; nt < 8; nt++) {
            int kcol = kc + nt*8 + t*2;
            float2 mbv = *(const float2*)&mb[kcol];
            #pragma unroll
            for (int mt = 0; mt < 2; mt++) {
                int row0 = q0 + mt*16 + g;
                float2 t0 = *(const float2*)&tbp[ row0     *NN + kcol];
                float2 t1 = *(const float2*)&tbp[(row0 + 8)*NN + kcol];
                float p0 = __expf(S[mt][nt][0] + mbv.x + t0.x);
                float p1 = __expf(S[mt][nt][1] + mbv.y + t0.y);
                float p2 = __expf(S[mt][nt][2] + mbv.x + t1.x);
                float p3 = __expf(S[mt][nt][3] + mbv.y + t1.y);
                S[mt][nt][0] = p0; S[mt][nt][1] = p1;
                S[mt][nt][2] = p2; S[mt][nt][3] = p3;
                lacc[mt][0] += p0 + p1;
                lacc[mt][1] += p2 + p3;
            }
        }
        // ---- O += P V ----
        #pragma unroll
        for (int kstep = 0; kstep < 8; kstep++) {
            uint32_t bv0[4], bv1[4];
            #pragma unroll
            for (int ntd = 0; ntd < 4; ntd++) {
                bv0[ntd] = __float_as_uint(Vs[(kc + kstep*8 + t    )*VS_STR + ntd*8 + g]);
                bv1[ntd] = __float_as_uint(Vs[(kc + kstep*8 + t + 4)*VS_STR + ntd*8 + g]);
            }
            int base = lane & ~3;
            #pragma unroll
            for (int mt = 0; mt < 2; mt++) {
                float d0 = S[mt][kstep][0], d1 = S[mt][kstep][1];
                float d2 = S[mt][kstep][2], d3 = S[mt][kstep][3];
                float s00 = __shfl_sync(0xffffffffu, d0, base | (t >> 1));
                float s01 = __shfl_sync(0xffffffffu, d1, base | (t >> 1));
                float s02 = __shfl_sync(0xffffffffu, d0, base | ((t >> 1) + 2));
                float s03 = __shfl_sync(0xffffffffu, d1, base | ((t >> 1) + 2));
                float s10 = __shfl_sync(0xffffffffu, d2, base | (t >> 1));
                float s11 = __shfl_sync(0xffffffffu, d3, base | (t >> 1));
                float s12 = __shfl_sync(0xffffffffu, d2, base | ((t >> 1) + 2));
                float s13 = __shfl_sync(0xffffffffu, d3, base | ((t >> 1) + 2));
                uint32_t ap[4];
                ap[0] = f2tf((t & 1) ? s01 : s00);
                ap[1] = f2tf((t & 1) ? s11 : s10);
                ap[2] = f2tf((t & 1) ? s03 : s02);
                ap[3] = f2tf((t & 1) ? s13 : s12);
                #pragma unroll
                for (int ntd = 0; ntd < 4; ntd++)
                    mma_tf32(Of[mt][ntd], ap, bv0[ntd], bv1[ntd]);
            }
        }
    }

    // ---- epilogue: final row-sum reduce, normalize, store ----
    float* obase = g_o + (size_t)(I*NN)*HD + h*DD;
    #pragma unroll
    for (int mt = 0; mt < 2; mt++) {
        float l0 = lacc[mt][0];
        l0 += __shfl_xor_sync(0xffffffffu, l0, 1);
        l0 += __shfl_xor_sync(0xffffffffu, l0, 2);
        float l1 = lacc[mt][1];
        l1 += __shfl_xor_sync(0xffffffffu, l1, 1);
        l1 += __shfl_xor_sync(0xffffffffu, l1, 2);
        float inv0 = 1.0f / l0;
        float inv1 = 1.0f / l1;
        int row0 = q0 + mt*16 + g;
        int row1 = row0 + 8;
        #pragma unroll
        for (int ntd = 0; ntd < 4; ntd++) {
            int col = ntd*8 + t*2;
            float2 w0 = make_float2(Of[mt][ntd][0]*inv0, Of[mt][ntd][1]*inv0);
            float2 w1 = make_float2(Of[mt][ntd][2]*inv1, Of[mt][ntd][3]*inv1);
            *(float2*)&obase[row0*HD + col] = w0;
            *(float2*)&obase[row1*HD + col] = w1;
        }
    }
}

// ---------------------------------------------------------------
// Kernel 4: gated output projection, tf32 mma + scatter epilogue
// ---------------------------------------------------------------
#define AS_STR 36
#define AS_SZ (128*AS_STR)
#define PROJ_SMEM ((AS_SZ + BS_SZ)*2*4)

__global__ __launch_bounds__(256, 2)
void gemm_out_tf32(const float* __restrict__ bg, const float* __restrict__ bo,
                   float* __restrict__ out)
{
    extern __shared__ float ps[];
    float* As = ps;
    float* Bs = ps + 2*AS_SZ;

    int m0 = blockIdx.x * 128;

    int tid = threadIdx.x;
    int warp = tid >> 5, lane = tid & 31;
    int g = lane >> 2, t = lane & 3;
    int wm = warp >> 2, wn = warp & 3;
    int mbase = wm*64, nbase = wn*32;

    float acc[4][4][4] = {};

    auto load_stage = [&](int buf, int k0) {
        float* A = As + buf*AS_SZ;
        float* B = Bs + buf*BS_SZ;
        #pragma unroll
        for (int i = 0; i < 4; i++) {
            int f = tid + 256*i;
            int mm = f >> 3;
            int kq = (f & 7) * 4;
            int row = m0 + mm;
            float4 o4  = *(const float4*)&g_o[row*HD + k0 + kq];
            float4 g4  = *(const float4*)&g_g[row*HD + k0 + kq];
            float4 bg4 = *(const float4*)&bg[k0 + kq];
            float4 a;
            a.x = f2tf_f(o4.x / (1.0f + __expf(-(g4.x + bg4.x))));
            a.y = f2tf_f(o4.y / (1.0f + __expf(-(g4.y + bg4.y))));
            a.z = f2tf_f(o4.z / (1.0f + __expf(-(g4.z + bg4.z))));
            a.w = f2tf_f(o4.w / (1.0f + __expf(-(g4.w + bg4.w))));
            *(float4*)&A[mm*AS_STR + kq] = a;
            int kk = f >> 5;
            int nq = (f & 31) * 4;
            *(float4*)&B[kk*BS_STR + nq] = *(const float4*)&g_woT[(k0 + kk)*HD + nq];
        }
    };

    load_stage(0, 0);
    __syncthreads();

    for (int st = 0; st < 4; st++) {
        if (st < 3) load_stage((st + 1) & 1, (st + 1) * 32);
        float* A = As + (st & 1)*AS_SZ;
        float* B = Bs + (st & 1)*BS_SZ;
        #pragma unroll
        for (int ks = 0; ks < 4; ks++) {
            uint32_t af[4][4];
            #pragma unroll
            for (int mt = 0; mt < 4; mt++) {
                int r0 = mbase + mt*16 + g;
                af[mt][0] = __float_as_uint(A[ r0     *AS_STR + ks*8 + t    ]);
                af[mt][1] = __float_as_uint(A[(r0 + 8)*AS_STR + ks*8 + t    ]);
                af[mt][2] = __float_as_uint(A[ r0     *AS_STR + ks*8 + t + 4]);
                af[mt][3] = __float_as_uint(A[(r0 + 8)*AS_STR + ks*8 + t + 4]);
            }
            uint32_t bf0[4], bf1[4];
            #pragma unroll
            for (int nt = 0; nt < 4; nt++) {
                int nc = nbase + nt*8 + g;
                bf0[nt] = __float_as_uint(B[(ks*8 + t    )*BS_STR + nc]);
                bf1[nt] = __float_as_uint(B[(ks*8 + t + 4)*BS_STR + nc]);
            }
            #pragma unroll
            for (int mt = 0; mt < 4; mt++)
                #pragma unroll
                for (int nt = 0; nt < 4; nt++)
                    mma_tf32(acc[mt][nt], af[mt], bf0[nt], bf1[nt]);
        }
        __syncthreads();
    }

    #pragma unroll
    for (int mt = 0; mt < 4; mt++) {
        int mr0 = m0 + mbase + mt*16 + g;
        int mr1 = mr0 + 8;
        int or0 = (mr0 & 255)*NN + (mr0 >> 8);   // swapaxes scatter
        int or1 = (mr1 & 255)*NN + (mr1 >> 8);
        #pragma unroll
        for (int nt = 0; nt < 4; nt++) {
            int col = nbase + nt*8 + 2*t;
            float2 b2 = *(const float2*)&bo[col];
            float2 w0 = make_float2(acc[mt][nt][0] + b2.x, acc[mt][nt][1] + b2.y);
            float2 w1 = make_float2(acc[mt][nt][2] + b2.x, acc[mt][nt][3] + b2.y);
            *(float2*)&out[or0*CC + col] = w0;
            *(float2*)&out[or1*CC + col] = w1;
        }
    }
}

// ---------------------------------------------------------------
extern "C" void kernel_launch(void* const* d_in, const int* in_sizes, int n_in,
                              void* d_out, int out_size)
{
    const float* x      = (const float*)d_in[0];
    const float* mask   = (const float*)d_in[1];
    const float* ln_w   = (const float*)d_in[2];
    const float* ln_b   = (const float*)d_in[3];
    const float* w_bias = (const float*)d_in[4];
    const float* wq     = (const float*)d_in[5];
    const float* wk     = (const float*)d_in[6];
    const float* wv     = (const float*)d_in[7];
    const float* wg     = (const float*)d_in[8];
    const float* bg     = (const float*)d_in[9];
    const float* wo     = (const float*)d_in[10];
    const float* bo     = (const float*)d_in[11];
    float* out = (float*)d_out;

    static bool attr_set = false;
    if (!attr_set) {
        cudaFuncSetAttribute(attn_mma, cudaFuncAttributeMaxDynamicSharedMemorySize,
                             ATTN_SMEM);
        cudaFuncSetAttribute(gemm_proj_fused, cudaFuncAttributeMaxDynamicSharedMemorySize,
                             PROJF_SMEM);
        cudaFuncSetAttribute(gemm_out_tf32, cudaFuncAttributeMaxDynamicSharedMemorySize,
                             PROJ_SMEM);
        attr_set = true;
    }

    gemm_proj_fused<<<dim3(MM/128, 4), 256, PROJF_SMEM>>>(x, ln_w, ln_b, w_bias,
                                                          wq, wk, wv, wg);
    transpose_wo<<<64, 256>>>(wo);
    attn_mma<<<dim3(NN, HH), 256, ATTN_SMEM>>>(mask);
    gemm_out_tf32<<<dim3(MM/128, 1), 256, PROJ_SMEM>>>(bg, bo, out);
}

// round 9
// speedup vs baseline: 1.1282x; 1.1282x over previous
#include <cuda_runtime.h>
#include <math.h>
#include <float.h>
#include <stdint.h>

#define NN 256
#define CC 128
#define HH 4
#define DD 32
#define MM (NN*NN)     // 65536
#define HD (HH*DD)     // 128
#define INF_ 1e9f
#define LN_EPS 1e-5f

// ---- scratch ----
__device__ float g_xn[MM*CC];       // tf32-rounded
__device__ float g_q [MM*HD];       // tf32-rounded, scale applied
__device__ float g_k [MM*HD];       // tf32-rounded
__device__ float g_v [MM*HD];       // tf32-rounded
__device__ float g_g [MM*HD];       // gate pre-sigmoid
__device__ float g_o [MM*HD];       // fp32
__device__ float g_tbt[HH*NN*NN];   // [h][j][k], fp32
__device__ float g_woT[CC*HD];      // [k][n] = wo[n][k] (tf32-rounded)

// ---------------------------------------------------------------
// tf32 helpers
// ---------------------------------------------------------------
__device__ __forceinline__ uint32_t f2tf(float x) {
    uint32_t r;
    asm("cvt.rna.tf32.f32 %0, %1;" : "=r"(r) : "f"(x));
    return r;
}
__device__ __forceinline__ float f2tf_f(float x) {
    return __uint_as_float(f2tf(x));
}

__device__ __forceinline__ void mma_tf32(float c[4], const uint32_t a[4],
                                         uint32_t b0, uint32_t b1) {
    asm volatile(
        "mma.sync.aligned.m16n8k8.row.col.f32.tf32.tf32.f32 "
        "{%0,%1,%2,%3}, {%4,%5,%6,%7}, {%8,%9}, {%0,%1,%2,%3};\n"
        : "+f"(c[0]), "+f"(c[1]), "+f"(c[2]), "+f"(c[3])
        : "r"(a[0]), "r"(a[1]), "r"(a[2]), "r"(a[3]), "r"(b0), "r"(b1));
}

// ---------------------------------------------------------------
// Kernel 1: LayerNorm (warp per row) + triangle-bias dots
// ---------------------------------------------------------------
__global__ __launch_bounds__(256)
void ln_kernel(const float* __restrict__ x,
               const float* __restrict__ ln_w,
               const float* __restrict__ ln_b,
               const float* __restrict__ w_bias)
{
    int warp = threadIdx.x >> 5, lane = threadIdx.x & 31;
    int m  = blockIdx.x * 8 + warp;
    int i1 = m >> 8;
    int i2 = m & 255;

    float4 v4 = *(const float4*)&x[(i2*NN + i1)*CC + lane*4];

    float s = v4.x + v4.y + v4.z + v4.w;
    #pragma unroll
    for (int o = 16; o > 0; o >>= 1) s += __shfl_xor_sync(0xffffffffu, s, o);
    float mu = s * (1.0f / CC);

    float dx = v4.x - mu, dy = v4.y - mu, dz = v4.z - mu, dw = v4.w - mu;
    float s2 = dx*dx + dy*dy + dz*dz + dw*dw;
    #pragma unroll
    for (int o = 16; o > 0; o >>= 1) s2 += __shfl_xor_sync(0xffffffffu, s2, o);
    float rs = rsqrtf(s2 * (1.0f / CC) + LN_EPS);

    float4 w4 = *(const float4*)&ln_w[lane*4];
    float4 b4 = *(const float4*)&ln_b[lane*4];
    float xn0 = dx*rs*w4.x + b4.x;
    float xn1 = dy*rs*w4.y + b4.y;
    float xn2 = dz*rs*w4.z + b4.z;
    float xn3 = dw*rs*w4.w + b4.w;

    *(float4*)&g_xn[m*CC + lane*4] =
        make_float4(f2tf_f(xn0), f2tf_f(xn1), f2tf_f(xn2), f2tf_f(xn3));

    // triangle bias dots (full precision); layout [h][j=i1][k=i2]
    float acc[4];
    #pragma unroll
    for (int h = 0; h < 4; h++) {
        float4 wb = *(const float4*)&w_bias[h*CC + lane*4];
        acc[h] = xn0*wb.x + xn1*wb.y + xn2*wb.z + xn3*wb.w;
    }
    #pragma unroll
    for (int o = 16; o > 0; o >>= 1) {
        #pragma unroll
        for (int h = 0; h < 4; h++)
            acc[h] += __shfl_xor_sync(0xffffffffu, acc[h], o);
    }
    if (lane < 4)
        g_tbt[(lane*NN + i1)*NN + i2] = acc[lane];
}

// ---------------------------------------------------------------
// Kernel 2: q/k/v/g projections, tf32 mma, 128x128 tile, dbl-buffered
// ---------------------------------------------------------------
#define AS_STR 36
#define BS_STR 136
#define AS_SZ (128*AS_STR)
#define BS_SZ (32*BS_STR)
#define PROJ_SMEM ((AS_SZ + BS_SZ)*2*4)

__global__ __launch_bounds__(256, 2)
void gemm_proj_tf32(const float* __restrict__ W0, const float* __restrict__ W1,
                    const float* __restrict__ W2, const float* __restrict__ W3)
{
    extern __shared__ float ps[];
    float* As = ps;
    float* Bs = ps + 2*AS_SZ;

    const float* W;
    float* Out;
    float osc = 1.0f;
    switch (blockIdx.y) {
        case 0: W = W0; Out = g_q; osc = 0.17677669529663689f; break;
        case 1: W = W1; Out = g_k; break;
        case 2: W = W2; Out = g_v; break;
        default: W = W3; Out = g_g; break;
    }
    int m0 = blockIdx.x * 128;

    int tid = threadIdx.x;
    int warp = tid >> 5, lane = tid & 31;
    int g = lane >> 2, t = lane & 3;
    int wm = warp >> 2, wn = warp & 3;
    int mbase = wm*64, nbase = wn*32;

    float acc[4][4][4] = {};

    auto load_stage = [&](int buf, int k0) {
        float* A = As + buf*AS_SZ;
        float* B = Bs + buf*BS_SZ;
        #pragma unroll
        for (int i = 0; i < 4; i++) {
            int f = tid + 256*i;
            int mm = f >> 3;
            int kq = (f & 7) * 4;
            float4 a = *(const float4*)&g_xn[(m0 + mm)*CC + k0 + kq];
            *(float4*)&A[mm*AS_STR + kq] = a;
            int kk = f >> 5;
            int nq = (f & 31) * 4;
            float4 b = *(const float4*)&W[(k0 + kk)*HD + nq];
            b.x = f2tf_f(b.x); b.y = f2tf_f(b.y);
            b.z = f2tf_f(b.z); b.w = f2tf_f(b.w);
            *(float4*)&B[kk*BS_STR + nq] = b;
        }
    };

    load_stage(0, 0);
    __syncthreads();

    for (int st = 0; st < 4; st++) {
        if (st < 3) load_stage((st + 1) & 1, (st + 1) * 32);
        float* A = As + (st & 1)*AS_SZ;
        float* B = Bs + (st & 1)*BS_SZ;
        #pragma unroll
        for (int ks = 0; ks < 4; ks++) {
            uint32_t af[4][4];
            #pragma unroll
            for (int mt = 0; mt < 4; mt++) {
                int r0 = mbase + mt*16 + g;
                af[mt][0] = __float_as_uint(A[ r0     *AS_STR + ks*8 + t    ]);
                af[mt][1] = __float_as_uint(A[(r0 + 8)*AS_STR + ks*8 + t    ]);
                af[mt][2] = __float_as_uint(A[ r0     *AS_STR + ks*8 + t + 4]);
                af[mt][3] = __float_as_uint(A[(r0 + 8)*AS_STR + ks*8 + t + 4]);
            }
            uint32_t bf0[4], bf1[4];
            #pragma unroll
            for (int nt = 0; nt < 4; nt++) {
                int nc = nbase + nt*8 + g;
                bf0[nt] = __float_as_uint(B[(ks*8 + t    )*BS_STR + nc]);
                bf1[nt] = __float_as_uint(B[(ks*8 + t + 4)*BS_STR + nc]);
            }
            #pragma unroll
            for (int mt = 0; mt < 4; mt++)
                #pragma unroll
                for (int nt = 0; nt < 4; nt++)
                    mma_tf32(acc[mt][nt], af[mt], bf0[nt], bf1[nt]);
        }
        __syncthreads();
    }

    #pragma unroll
    for (int mt = 0; mt < 4; mt++) {
        int row0 = m0 + mbase + mt*16 + g;
        int row1 = row0 + 8;
        #pragma unroll
        for (int nt = 0; nt < 4; nt++) {
            int col = nbase + nt*8 + 2*t;
            float2 w0 = make_float2(f2tf_f(acc[mt][nt][0]*osc), f2tf_f(acc[mt][nt][1]*osc));
            float2 w1 = make_float2(f2tf_f(acc[mt][nt][2]*osc), f2tf_f(acc[mt][nt][3]*osc));
            *(float2*)&Out[row0*HD + col] = w0;
            *(float2*)&Out[row1*HD + col] = w1;
        }
    }
}

// ---------------------------------------------------------------
// Kernel 3: wo transpose
// ---------------------------------------------------------------
__global__ void transpose_wo(const float* __restrict__ wo)
{
    int idx = blockIdx.x * 256 + threadIdx.x;
    int n = idx >> 7, k = idx & 127;
    g_woT[k*HD + n] = f2tf_f(wo[n*HD + k]);
}

// ---------------------------------------------------------------
// Kernel 4: tf32 mma flash attention, 8 warps x 32 queries,
// no-max softmax, thread-local row-sum accumulation.
// ---------------------------------------------------------------
#define KS_STR 36
#define VS_STR 40
#define ATTN_SMEM ((NN*KS_STR + NN*VS_STR + NN) * 4)

__global__ __launch_bounds__(256)
void attn_mma(const float* __restrict__ mask)
{
    extern __shared__ float sm[];
    float* Ks = sm;                         // [256][36]
    float* Vs = sm + NN*KS_STR;             // [256][40]
    float* mb = sm + NN*KS_STR + NN*VS_STR; // [256]

    int I = blockIdx.x, h = blockIdx.y;
    int tid  = threadIdx.x;
    int warp = tid >> 5, lane = tid & 31;
    int g = lane >> 2, t = lane & 3;

    const float* kbase = g_k + (size_t)(I*NN)*HD + h*DD;
    const float* vbase = g_v + (size_t)(I*NN)*HD + h*DD;
    #pragma unroll
    for (int p = 0; p < 8; p++) {
        int slot = p*256 + tid;             // 0..2047
        int key = slot >> 3;
        int d4  = (slot & 7) * 4;
        *(float4*)&Ks[key*KS_STR + d4] = *(const float4*)&kbase[key*HD + d4];
        *(float4*)&Vs[key*VS_STR + d4] = *(const float4*)&vbase[key*HD + d4];
    }
    mb[tid] = INF_ * (mask[tid*NN + I] - 1.0f);

    int q0 = warp * 32;
    const float* qbase = g_q + (size_t)(I*NN)*HD + h*DD;
    uint32_t aq[2][4][4];
    #pragma unroll
    for (int mt = 0; mt < 2; mt++)
        #pragma unroll
        for (int ks = 0; ks < 4; ks++)
            #pragma unroll
            for (int r = 0; r < 4; r++) {
                int row = q0 + mt*16 + (r & 1)*8 + g;
                int col = ks*8 + t + (r >> 1)*4;
                aq[mt][ks][r] = __float_as_uint(qbase[row*HD + col]);
            }

    float Of[2][4][4] = {};
    float lacc[2][2] = {};

    const float* tbp = g_tbt + h*NN*NN;     // [j][k]

    __syncthreads();

    for (int kc = 0; kc < NN; kc += 64) {
        // ---- S = Q K^T ----
        float S[2][8][4] = {};
        #pragma unroll
        for (int nt = 0; nt < 8; nt++) {
            int n0 = kc + nt*8;
            #pragma unroll
            for (int ks = 0; ks < 4; ks++) {
                uint32_t b0 = __float_as_uint(Ks[(n0 + g)*KS_STR + ks*8 + t]);
                uint32_t b1 = __float_as_uint(Ks[(n0 + g)*KS_STR + ks*8 + t + 4]);
                mma_tf32(S[0][nt], aq[0][ks], b0, b1);
                mma_tf32(S[1][nt], aq[1][ks], b0, b1);
            }
        }
        // ---- biases + exp + row-sum accumulation ----
        #pragma unroll
        for (int nt = 0; nt < 8; nt++) {
            int kcol = kc + nt*8 + t*2;
            float2 mbv = *(const float2*)&mb[kcol];
            #pragma unroll
            for (int mt = 0; mt < 2; mt++) {
                int row0 = q0 + mt*16 + g;
                float2 t0 = *(const float2*)&tbp[ row0     *NN + kcol];
                float2 t1 = *(const float2*)&tbp[(row0 + 8)*NN + kcol];
                float p0 = __expf(S[mt][nt][0] + mbv.x + t0.x);
                float p1 = __expf(S[mt][nt][1] + mbv.y + t0.y);
                float p2 = __expf(S[mt][nt][2] + mbv.x + t1.x);
                float p3 = __expf(S[mt][nt][3] + mbv.y + t1.y);
                S[mt][nt][0] = p0; S[mt][nt][1] = p1;
                S[mt][nt][2] = p2; S[mt][nt][3] = p3;
                lacc[mt][0] += p0 + p1;
                lacc[mt][1] += p2 + p3;
            }
        }
        // ---- O += P V ----
        #pragma unroll
        for (int kstep = 0; kstep < 8; kstep++) {
            uint32_t bv0[4], bv1[4];
            #pragma unroll
            for (int ntd = 0; ntd < 4; ntd++) {
                bv0[ntd] = __float_as_uint(Vs[(kc + kstep*8 + t    )*VS_STR + ntd*8 + g]);
                bv1[ntd] = __float_as_uint(Vs[(kc + kstep*8 + t + 4)*VS_STR + ntd*8 + g]);
            }
            int base = lane & ~3;
            #pragma unroll
            for (int mt = 0; mt < 2; mt++) {
                float d0 = S[mt][kstep][0], d1 = S[mt][kstep][1];
                float d2 = S[mt][kstep][2], d3 = S[mt][kstep][3];
                float s00 = __shfl_sync(0xffffffffu, d0, base | (t >> 1));
                float s01 = __shfl_sync(0xffffffffu, d1, base | (t >> 1));
                float s02 = __shfl_sync(0xffffffffu, d0, base | ((t >> 1) + 2));
                float s03 = __shfl_sync(0xffffffffu, d1, base | ((t >> 1) + 2));
                float s10 = __shfl_sync(0xffffffffu, d2, base | (t >> 1));
                float s11 = __shfl_sync(0xffffffffu, d3, base | (t >> 1));
                float s12 = __shfl_sync(0xffffffffu, d2, base | ((t >> 1) + 2));
                float s13 = __shfl_sync(0xffffffffu, d3, base | ((t >> 1) + 2));
                uint32_t ap[4];
                ap[0] = f2tf((t & 1) ? s01 : s00);
                ap[1] = f2tf((t & 1) ? s11 : s10);
                ap[2] = f2tf((t & 1) ? s03 : s02);
                ap[3] = f2tf((t & 1) ? s13 : s12);
                #pragma unroll
                for (int ntd = 0; ntd < 4; ntd++)
                    mma_tf32(Of[mt][ntd], ap, bv0[ntd], bv1[ntd]);
            }
        }
    }

    // ---- epilogue ----
    float* obase = g_o + (size_t)(I*NN)*HD + h*DD;
    #pragma unroll
    for (int mt = 0; mt < 2; mt++) {
        float l0 = lacc[mt][0];
        l0 += __shfl_xor_sync(0xffffffffu, l0, 1);
        l0 += __shfl_xor_sync(0xffffffffu, l0, 2);
        float l1 = lacc[mt][1];
        l1 += __shfl_xor_sync(0xffffffffu, l1, 1);
        l1 += __shfl_xor_sync(0xffffffffu, l1, 2);
        float inv0 = 1.0f / l0;
        float inv1 = 1.0f / l1;
        int row0 = q0 + mt*16 + g;
        int row1 = row0 + 8;
        #pragma unroll
        for (int ntd = 0; ntd < 4; ntd++) {
            int col = ntd*8 + t*2;
            float2 w0 = make_float2(Of[mt][ntd][0]*inv0, Of[mt][ntd][1]*inv0);
            float2 w1 = make_float2(Of[mt][ntd][2]*inv1, Of[mt][ntd][3]*inv1);
            *(float2*)&obase[row0*HD + col] = w0;
            *(float2*)&obase[row1*HD + col] = w1;
        }
    }
}

// ---------------------------------------------------------------
// Kernel 5: gated output projection, tf32 mma + scatter epilogue
// ---------------------------------------------------------------
__global__ __launch_bounds__(256, 2)
void gemm_out_tf32(const float* __restrict__ bg, const float* __restrict__ bo,
                   float* __restrict__ out)
{
    extern __shared__ float ps[];
    float* As = ps;
    float* Bs = ps + 2*AS_SZ;

    int m0 = blockIdx.x * 128;

    int tid = threadIdx.x;
    int warp = tid >> 5, lane = tid & 31;
    int g = lane >> 2, t = lane & 3;
    int wm = warp >> 2, wn = warp & 3;
    int mbase = wm*64, nbase = wn*32;

    float acc[4][4][4] = {};

    auto load_stage = [&](int buf, int k0) {
        float* A = As + buf*AS_SZ;
        float* B = Bs + buf*BS_SZ;
        #pragma unroll
        for (int i = 0; i < 4; i++) {
            int f = tid + 256*i;
            int mm = f >> 3;
            int kq = (f & 7) * 4;
            int row = m0 + mm;
            float4 o4  = *(const float4*)&g_o[row*HD + k0 + kq];
            float4 g4  = *(const float4*)&g_g[row*HD + k0 + kq];
            float4 bg4 = *(const float4*)&bg[k0 + kq];
            float4 a;
            a.x = f2tf_f(o4.x / (1.0f + __expf(-(g4.x + bg4.x))));
            a.y = f2tf_f(o4.y / (1.0f + __expf(-(g4.y + bg4.y))));
            a.z = f2tf_f(o4.z / (1.0f + __expf(-(g4.z + bg4.z))));
            a.w = f2tf_f(o4.w / (1.0f + __expf(-(g4.w + bg4.w))));
            *(float4*)&A[mm*AS_STR + kq] = a;
            int kk = f >> 5;
            int nq = (f & 31) * 4;
            *(float4*)&B[kk*BS_STR + nq] = *(const float4*)&g_woT[(k0 + kk)*HD + nq];
        }
    };

    load_stage(0, 0);
    __syncthreads();

    for (int st = 0; st < 4; st++) {
        if (st < 3) load_stage((st + 1) & 1, (st + 1) * 32);
        float* A = As + (st & 1)*AS_SZ;
        float* B = Bs + (st & 1)*BS_SZ;
        #pragma unroll
        for (int ks = 0; ks < 4; ks++) {
            uint32_t af[4][4];
            #pragma unroll
            for (int mt = 0; mt < 4; mt++) {
                int r0 = mbase + mt*16 + g;
                af[mt][0] = __float_as_uint(A[ r0     *AS_STR + ks*8 + t    ]);
                af[mt][1] = __float_as_uint(A[(r0 + 8)*AS_STR + ks*8 + t    ]);
                af[mt][2] = __float_as_uint(A[ r0     *AS_STR + ks*8 + t + 4]);
                af[mt][3] = __float_as_uint(A[(r0 + 8)*AS_STR + ks*8 + t + 4]);
            }
            uint32_t bf0[4], bf1[4];
            #pragma unroll
            for (int nt = 0; nt < 4; nt++) {
                int nc = nbase + nt*8 + g;
                bf0[nt] = __float_as_uint(B[(ks*8 + t    )*BS_STR + nc]);
                bf1[nt] = __float_as_uint(B[(ks*8 + t + 4)*BS_STR + nc]);
            }
            #pragma unroll
            for (int mt = 0; mt < 4; mt++)
                #pragma unroll
                for (int nt = 0; nt < 4; nt++)
                    mma_tf32(acc[mt][nt], af[mt], bf0[nt], bf1[nt]);
        }
        __syncthreads();
    }

    #pragma unroll
    for (int mt = 0; mt < 4; mt++) {
        int mr0 = m0 + mbase + mt*16 + g;
        int mr1 = mr0 + 8;
        int or0 = (mr0 & 255)*NN + (mr0 >> 8);   // swapaxes scatter
        int or1 = (mr1 & 255)*NN + (mr1 >> 8);
        #pragma unroll
        for (int nt = 0; nt < 4; nt++) {
            int col = nbase + nt*8 + 2*t;
            float2 b2 = *(const float2*)&bo[col];
            float2 w0 = make_float2(acc[mt][nt][0] + b2.x, acc[mt][nt][1] + b2.y);
            float2 w1 = make_float2(acc[mt][nt][2] + b2.x, acc[mt][nt][3] + b2.y);
            *(float2*)&out[or0*CC + col] = w0;
            *(float2*)&out[or1*CC + col] = w1;
        }
    }
}

// ---------------------------------------------------------------
extern "C" void kernel_launch(void* const* d_in, const int* in_sizes, int n_in,
                              void* d_out, int out_size)
{
    const float* x      = (const float*)d_in[0];
    const float* mask   = (const float*)d_in[1];
    const float* ln_w   = (const float*)d_in[2];
    const float* ln_b   = (const float*)d_in[3];
    const float* w_bias = (const float*)d_in[4];
    const float* wq     = (const float*)d_in[5];
    const float* wk     = (const float*)d_in[6];
    const float* wv     = (const float*)d_in[7];
    const float* wg     = (const float*)d_in[8];
    const float* bg     = (const float*)d_in[9];
    const float* wo     = (const float*)d_in[10];
    const float* bo     = (const float*)d_in[11];
    float* out = (float*)d_out;

    static bool attr_set = false;
    if (!attr_set) {
        cudaFuncSetAttribute(attn_mma, cudaFuncAttributeMaxDynamicSharedMemorySize,
                             ATTN_SMEM);
        cudaFuncSetAttribute(gemm_proj_tf32, cudaFuncAttributeMaxDynamicSharedMemorySize,
                             PROJ_SMEM);
        cudaFuncSetAttribute(gemm_out_tf32, cudaFuncAttributeMaxDynamicSharedMemorySize,
                             PROJ_SMEM);
        attr_set = true;
    }

    ln_kernel<<<MM/8, 256>>>(x, ln_w, ln_b, w_bias);
    gemm_proj_tf32<<<dim3(MM/128, 4), 256, PROJ_SMEM>>>(wq, wk, wv, wg);
    transpose_wo<<<64, 256>>>(wo);
    attn_mma<<<dim3(NN, HH), 256, ATTN_SMEM>>>(mask);
    gemm_out_tf32<<<dim3(MM/128, 1), 256, PROJ_SMEM>>>(bg, bo, out);
}

// round 10
// speedup vs baseline: 1.3419x; 1.1895x over previous
#include <cuda_runtime.h>
#include <math.h>
#include <float.h>
#include <stdint.h>

#define NN 256
#define CC 128
#define HH 4
#define DD 32
#define MM (NN*NN)     // 65536
#define HD (HH*DD)     // 128
#define INF_ 1e9f
#define LN_EPS 1e-5f

// ---- scratch ----
__device__ float g_xn[MM*CC];       // tf32-rounded
__device__ float g_q [MM*HD];       // tf32-rounded, scale applied
__device__ float g_k [MM*HD];       // tf32-rounded
__device__ float g_v [MM*HD];       // tf32-rounded
__device__ float g_g [MM*HD];       // gate pre-sigmoid
__device__ float g_o [MM*HD];       // fp32
__device__ float g_tbt[HH*NN*NN];   // [h][j][k], fp32
__device__ float g_woT[CC*HD];      // [k][n] = wo[n][k] (tf32-rounded)

// ---------------------------------------------------------------
// tf32 helpers
// ---------------------------------------------------------------
__device__ __forceinline__ uint32_t f2tf(float x) {
    uint32_t r;
    asm("cvt.rna.tf32.f32 %0, %1;" : "=r"(r) : "f"(x));
    return r;
}
__device__ __forceinline__ float f2tf_f(float x) {
    return __uint_as_float(f2tf(x));
}

__device__ __forceinline__ void mma_tf32(float c[4], const uint32_t a[4],
                                         uint32_t b0, uint32_t b1) {
    asm volatile(
        "mma.sync.aligned.m16n8k8.row.col.f32.tf32.tf32.f32 "
        "{%0,%1,%2,%3}, {%4,%5,%6,%7}, {%8,%9}, {%0,%1,%2,%3};\n"
        : "+f"(c[0]), "+f"(c[1]), "+f"(c[2]), "+f"(c[3])
        : "r"(a[0]), "r"(a[1]), "r"(a[2]), "r"(a[3]), "r"(b0), "r"(b1));
}

// ---------------------------------------------------------------
// Kernel 1: LayerNorm (warp per row) + triangle-bias dots
// ---------------------------------------------------------------
__global__ __launch_bounds__(256)
void ln_kernel(const float* __restrict__ x,
               const float* __restrict__ ln_w,
               const float* __restrict__ ln_b,
               const float* __restrict__ w_bias)
{
    int warp = threadIdx.x >> 5, lane = threadIdx.x & 31;
    int m  = blockIdx.x * 8 + warp;
    int i1 = m >> 8;
    int i2 = m & 255;

    float4 v4 = *(const float4*)&x[(i2*NN + i1)*CC + lane*4];

    float s = v4.x + v4.y + v4.z + v4.w;
    #pragma unroll
    for (int o = 16; o > 0; o >>= 1) s += __shfl_xor_sync(0xffffffffu, s, o);
    float mu = s * (1.0f / CC);

    float dx = v4.x - mu, dy = v4.y - mu, dz = v4.z - mu, dw = v4.w - mu;
    float s2 = dx*dx + dy*dy + dz*dz + dw*dw;
    #pragma unroll
    for (int o = 16; o > 0; o >>= 1) s2 += __shfl_xor_sync(0xffffffffu, s2, o);
    float rs = rsqrtf(s2 * (1.0f / CC) + LN_EPS);

    float4 w4 = *(const float4*)&ln_w[lane*4];
    float4 b4 = *(const float4*)&ln_b[lane*4];
    float xn0 = dx*rs*w4.x + b4.x;
    float xn1 = dy*rs*w4.y + b4.y;
    float xn2 = dz*rs*w4.z + b4.z;
    float xn3 = dw*rs*w4.w + b4.w;

    *(float4*)&g_xn[m*CC + lane*4] =
        make_float4(f2tf_f(xn0), f2tf_f(xn1), f2tf_f(xn2), f2tf_f(xn3));

    // triangle bias dots; layout [h][j=i1][k=i2]
    float acc[4];
    #pragma unroll
    for (int h = 0; h < 4; h++) {
        float4 wb = *(const float4*)&w_bias[h*CC + lane*4];
        acc[h] = xn0*wb.x + xn1*wb.y + xn2*wb.z + xn3*wb.w;
    }
    #pragma unroll
    for (int o = 16; o > 0; o >>= 1) {
        #pragma unroll
        for (int h = 0; h < 4; h++)
            acc[h] += __shfl_xor_sync(0xffffffffu, acc[h], o);
    }
    if (lane < 4)
        g_tbt[(lane*NN + i1)*NN + i2] = acc[lane];
}

// ---------------------------------------------------------------
// Kernel 2: q/k/v/g projections, tf32 mma, 128x128 tile, dbl-buffered
// ---------------------------------------------------------------
#define AS_STR 36
#define BS_STR 136
#define AS_SZ (128*AS_STR)
#define BS_SZ (32*BS_STR)
#define PROJ_SMEM ((AS_SZ + BS_SZ)*2*4)

__global__ __launch_bounds__(256, 2)
void gemm_proj_tf32(const float* __restrict__ W0, const float* __restrict__ W1,
                    const float* __restrict__ W2, const float* __restrict__ W3)
{
    extern __shared__ float ps[];
    float* As = ps;
    float* Bs = ps + 2*AS_SZ;

    const float* W;
    float* Out;
    float osc = 1.0f;
    switch (blockIdx.y) {
        case 0: W = W0; Out = g_q; osc = 0.17677669529663689f; break;
        case 1: W = W1; Out = g_k; break;
        case 2: W = W2; Out = g_v; break;
        default: W = W3; Out = g_g; break;
    }
    int m0 = blockIdx.x * 128;

    int tid = threadIdx.x;
    int warp = tid >> 5, lane = tid & 31;
    int g = lane >> 2, t = lane & 3;
    int wm = warp >> 2, wn = warp & 3;
    int mbase = wm*64, nbase = wn*32;

    float acc[4][4][4] = {};

    auto load_stage = [&](int buf, int k0) {
        float* A = As + buf*AS_SZ;
        float* B = Bs + buf*BS_SZ;
        #pragma unroll
        for (int i = 0; i < 4; i++) {
            int f = tid + 256*i;
            int mm = f >> 3;
            int kq = (f & 7) * 4;
            float4 a = *(const float4*)&g_xn[(m0 + mm)*CC + k0 + kq];
            *(float4*)&A[mm*AS_STR + kq] = a;
            int kk = f >> 5;
            int nq = (f & 31) * 4;
            float4 b = *(const float4*)&W[(k0 + kk)*HD + nq];
            b.x = f2tf_f(b.x); b.y = f2tf_f(b.y);
            b.z = f2tf_f(b.z); b.w = f2tf_f(b.w);
            *(float4*)&B[kk*BS_STR + nq] = b;
        }
    };

    load_stage(0, 0);
    __syncthreads();

    for (int st = 0; st < 4; st++) {
        if (st < 3) load_stage((st + 1) & 1, (st + 1) * 32);
        float* A = As + (st & 1)*AS_SZ;
        float* B = Bs + (st & 1)*BS_SZ;
        #pragma unroll
        for (int ks = 0; ks < 4; ks++) {
            uint32_t af[4][4];
            #pragma unroll
            for (int mt = 0; mt < 4; mt++) {
                int r0 = mbase + mt*16 + g;
                af[mt][0] = __float_as_uint(A[ r0     *AS_STR + ks*8 + t    ]);
                af[mt][1] = __float_as_uint(A[(r0 + 8)*AS_STR + ks*8 + t    ]);
                af[mt][2] = __float_as_uint(A[ r0     *AS_STR + ks*8 + t + 4]);
                af[mt][3] = __float_as_uint(A[(r0 + 8)*AS_STR + ks*8 + t + 4]);
            }
            uint32_t bf0[4], bf1[4];
            #pragma unroll
            for (int nt = 0; nt < 4; nt++) {
                int nc = nbase + nt*8 + g;
                bf0[nt] = __float_as_uint(B[(ks*8 + t    )*BS_STR + nc]);
                bf1[nt] = __float_as_uint(B[(ks*8 + t + 4)*BS_STR + nc]);
            }
            #pragma unroll
            for (int mt = 0; mt < 4; mt++)
                #pragma unroll
                for (int nt = 0; nt < 4; nt++)
                    mma_tf32(acc[mt][nt], af[mt], bf0[nt], bf1[nt]);
        }
        __syncthreads();
    }

    #pragma unroll
    for (int mt = 0; mt < 4; mt++) {
        int row0 = m0 + mbase + mt*16 + g;
        int row1 = row0 + 8;
        #pragma unroll
        for (int nt = 0; nt < 4; nt++) {
            int col = nbase + nt*8 + 2*t;
            float2 w0 = make_float2(f2tf_f(acc[mt][nt][0]*osc), f2tf_f(acc[mt][nt][1]*osc));
            float2 w1 = make_float2(f2tf_f(acc[mt][nt][2]*osc), f2tf_f(acc[mt][nt][3]*osc));
            *(float2*)&Out[row0*HD + col] = w0;
            *(float2*)&Out[row1*HD + col] = w1;
        }
    }
}

// ---------------------------------------------------------------
// Kernel 3: wo transpose
// ---------------------------------------------------------------
__global__ void transpose_wo(const float* __restrict__ wo)
{
    int idx = blockIdx.x * 256 + threadIdx.x;
    int n = idx >> 7, k = idx & 127;
    g_woT[k*HD + n] = f2tf_f(wo[n*HD + k]);
}

// ---------------------------------------------------------------
// Kernel 4: tf32 mma flash attention, 8 warps x 32 queries,
// 32-key chunks (S fits 32 regs) + launch_bounds(256,2) -> 2 blocks/SM.
// No-max softmax, thread-local row sums.
// ---------------------------------------------------------------
#define KS_STR 36
#define VS_STR 40
#define ATTN_SMEM ((NN*KS_STR + NN*VS_STR + NN) * 4)

__global__ __launch_bounds__(256, 2)
void attn_mma(const float* __restrict__ mask)
{
    extern __shared__ float sm[];
    float* Ks = sm;                         // [256][36]
    float* Vs = sm + NN*KS_STR;             // [256][40]
    float* mb = sm + NN*KS_STR + NN*VS_STR; // [256]

    int I = blockIdx.x, h = blockIdx.y;
    int tid  = threadIdx.x;
    int warp = tid >> 5, lane = tid & 31;
    int g = lane >> 2, t = lane & 3;

    const float* kbase = g_k + (size_t)(I*NN)*HD + h*DD;
    const float* vbase = g_v + (size_t)(I*NN)*HD + h*DD;
    #pragma unroll
    for (int p = 0; p < 8; p++) {
        int slot = p*256 + tid;             // 0..2047
        int key = slot >> 3;
        int d4  = (slot & 7) * 4;
        *(float4*)&Ks[key*KS_STR + d4] = *(const float4*)&kbase[key*HD + d4];
        *(float4*)&Vs[key*VS_STR + d4] = *(const float4*)&vbase[key*HD + d4];
    }
    mb[tid] = INF_ * (mask[tid*NN + I] - 1.0f);

    int q0 = warp * 32;
    const float* qbase = g_q + (size_t)(I*NN)*HD + h*DD;
    uint32_t aq[2][4][4];
    #pragma unroll
    for (int mt = 0; mt < 2; mt++)
        #pragma unroll
        for (int ks = 0; ks < 4; ks++)
            #pragma unroll
            for (int r = 0; r < 4; r++) {
                int row = q0 + mt*16 + (r & 1)*8 + g;
                int col = ks*8 + t + (r >> 1)*4;
                aq[mt][ks][r] = __float_as_uint(qbase[row*HD + col]);
            }

    float Of[2][4][4] = {};
    float lacc[2][2] = {};

    const float* tbp = g_tbt + h*NN*NN;     // [j][k]

    __syncthreads();

    for (int kc = 0; kc < NN; kc += 32) {
        // ---- S = Q K^T (32-key chunk) ----
        float S[2][4][4] = {};
        #pragma unroll
        for (int nt = 0; nt < 4; nt++) {
            int n0 = kc + nt*8;
            #pragma unroll
            for (int ks = 0; ks < 4; ks++) {
                uint32_t b0 = __float_as_uint(Ks[(n0 + g)*KS_STR + ks*8 + t]);
                uint32_t b1 = __float_as_uint(Ks[(n0 + g)*KS_STR + ks*8 + t + 4]);
                mma_tf32(S[0][nt], aq[0][ks], b0, b1);
                mma_tf32(S[1][nt], aq[1][ks], b0, b1);
            }
        }
        // ---- biases + exp + row-sum accumulation ----
        #pragma unroll
        for (int nt = 0; nt < 4; nt++) {
            int kcol = kc + nt*8 + t*2;
            float2 mbv = *(const float2*)&mb[kcol];
            #pragma unroll
            for (int mt = 0; mt < 2; mt++) {
                int row0 = q0 + mt*16 + g;
                float2 t0 = *(const float2*)&tbp[ row0     *NN + kcol];
                float2 t1 = *(const float2*)&tbp[(row0 + 8)*NN + kcol];
                float p0 = __expf(S[mt][nt][0] + mbv.x + t0.x);
                float p1 = __expf(S[mt][nt][1] + mbv.y + t0.y);
                float p2 = __expf(S[mt][nt][2] + mbv.x + t1.x);
                float p3 = __expf(S[mt][nt][3] + mbv.y + t1.y);
                S[mt][nt][0] = p0; S[mt][nt][1] = p1;
                S[mt][nt][2] = p2; S[mt][nt][3] = p3;
                lacc[mt][0] += p0 + p1;
                lacc[mt][1] += p2 + p3;
            }
        }
        // ---- O += P V ----
        #pragma unroll
        for (int kstep = 0; kstep < 4; kstep++) {
            uint32_t bv0[4], bv1[4];
            #pragma unroll
            for (int ntd = 0; ntd < 4; ntd++) {
                bv0[ntd] = __float_as_uint(Vs[(kc + kstep*8 + t    )*VS_STR + ntd*8 + g]);
                bv1[ntd] = __float_as_uint(Vs[(kc + kstep*8 + t + 4)*VS_STR + ntd*8 + g]);
            }
            int base = lane & ~3;
            #pragma unroll
            for (int mt = 0; mt < 2; mt++) {
                float d0 = S[mt][kstep][0], d1 = S[mt][kstep][1];
                float d2 = S[mt][kstep][2], d3 = S[mt][kstep][3];
                float s00 = __shfl_sync(0xffffffffu, d0, base | (t >> 1));
                float s01 = __shfl_sync(0xffffffffu, d1, base | (t >> 1));
                float s02 = __shfl_sync(0xffffffffu, d0, base | ((t >> 1) + 2));
                float s03 = __shfl_sync(0xffffffffu, d1, base | ((t >> 1) + 2));
                float s10 = __shfl_sync(0xffffffffu, d2, base | (t >> 1));
                float s11 = __shfl_sync(0xffffffffu, d3, base | (t >> 1));
                float s12 = __shfl_sync(0xffffffffu, d2, base | ((t >> 1) + 2));
                float s13 = __shfl_sync(0xffffffffu, d3, base | ((t >> 1) + 2));
                uint32_t ap[4];
                ap[0] = f2tf((t & 1) ? s01 : s00);
                ap[1] = f2tf((t & 1) ? s11 : s10);
                ap[2] = f2tf((t & 1) ? s03 : s02);
                ap[3] = f2tf((t & 1) ? s13 : s12);
                #pragma unroll
                for (int ntd = 0; ntd < 4; ntd++)
                    mma_tf32(Of[mt][ntd], ap, bv0[ntd], bv1[ntd]);
            }
        }
    }

    // ---- epilogue ----
    float* obase = g_o + (size_t)(I*NN)*HD + h*DD;
    #pragma unroll
    for (int mt = 0; mt < 2; mt++) {
        float l0 = lacc[mt][0];
        l0 += __shfl_xor_sync(0xffffffffu, l0, 1);
        l0 += __shfl_xor_sync(0xffffffffu, l0, 2);
        float l1 = lacc[mt][1];
        l1 += __shfl_xor_sync(0xffffffffu, l1, 1);
        l1 += __shfl_xor_sync(0xffffffffu, l1, 2);
        float inv0 = 1.0f / l0;
        float inv1 = 1.0f / l1;
        int row0 = q0 + mt*16 + g;
        int row1 = row0 + 8;
        #pragma unroll
        for (int ntd = 0; ntd < 4; ntd++) {
            int col = ntd*8 + t*2;
            float2 w0 = make_float2(Of[mt][ntd][0]*inv0, Of[mt][ntd][1]*inv0);
            float2 w1 = make_float2(Of[mt][ntd][2]*inv1, Of[mt][ntd][3]*inv1);
            *(float2*)&obase[row0*HD + col] = w0;
            *(float2*)&obase[row1*HD + col] = w1;
        }
    }
}

// ---------------------------------------------------------------
// Kernel 5: gated output projection, tf32 mma + scatter epilogue
// ---------------------------------------------------------------
__global__ __launch_bounds__(256, 2)
void gemm_out_tf32(const float* __restrict__ bg, const float* __restrict__ bo,
                   float* __restrict__ out)
{
    extern __shared__ float ps[];
    float* As = ps;
    float* Bs = ps + 2*AS_SZ;

    int m0 = blockIdx.x * 128;

    int tid = threadIdx.x;
    int warp = tid >> 5, lane = tid & 31;
    int g = lane >> 2, t = lane & 3;
    int wm = warp >> 2, wn = warp & 3;
    int mbase = wm*64, nbase = wn*32;

    float acc[4][4][4] = {};

    auto load_stage = [&](int buf, int k0) {
        float* A = As + buf*AS_SZ;
        float* B = Bs + buf*BS_SZ;
        #pragma unroll
        for (int i = 0; i < 4; i++) {
            int f = tid + 256*i;
            int mm = f >> 3;
            int kq = (f & 7) * 4;
            int row = m0 + mm;
            float4 o4  = *(const float4*)&g_o[row*HD + k0 + kq];
            float4 g4  = *(const float4*)&g_g[row*HD + k0 + kq];
            float4 bg4 = *(const float4*)&bg[k0 + kq];
            float4 a;
            a.x = f2tf_f(o4.x / (1.0f + __expf(-(g4.x + bg4.x))));
            a.y = f2tf_f(o4.y / (1.0f + __expf(-(g4.y + bg4.y))));
            a.z = f2tf_f(o4.z / (1.0f + __expf(-(g4.z + bg4.z))));
            a.w = f2tf_f(o4.w / (1.0f + __expf(-(g4.w + bg4.w))));
            *(float4*)&A[mm*AS_STR + kq] = a;
            int kk = f >> 5;
            int nq = (f & 31) * 4;
            *(float4*)&B[kk*BS_STR + nq] = *(const float4*)&g_woT[(k0 + kk)*HD + nq];
        }
    };

    load_stage(0, 0);
    __syncthreads();

    for (int st = 0; st < 4; st++) {
        if (st < 3) load_stage((st + 1) & 1, (st + 1) * 32);
        float* A = As + (st & 1)*AS_SZ;
        float* B = Bs + (st & 1)*BS_SZ;
        #pragma unroll
        for (int ks = 0; ks < 4; ks++) {
            uint32_t af[4][4];
            #pragma unroll
            for (int mt = 0; mt < 4; mt++) {
                int r0 = mbase + mt*16 + g;
                af[mt][0] = __float_as_uint(A[ r0     *AS_STR + ks*8 + t    ]);
                af[mt][1] = __float_as_uint(A[(r0 + 8)*AS_STR + ks*8 + t    ]);
                af[mt][2] = __float_as_uint(A[ r0     *AS_STR + ks*8 + t + 4]);
                af[mt][3] = __float_as_uint(A[(r0 + 8)*AS_STR + ks*8 + t + 4]);
            }
            uint32_t bf0[4], bf1[4];
            #pragma unroll
            for (int nt = 0; nt < 4; nt++) {
                int nc = nbase + nt*8 + g;
                bf0[nt] = __float_as_uint(B[(ks*8 + t    )*BS_STR + nc]);
                bf1[nt] = __float_as_uint(B[(ks*8 + t + 4)*BS_STR + nc]);
            }
            #pragma unroll
            for (int mt = 0; mt < 4; mt++)
                #pragma unroll
                for (int nt = 0; nt < 4; nt++)
                    mma_tf32(acc[mt][nt], af[mt], bf0[nt], bf1[nt]);
        }
        __syncthreads();
    }

    #pragma unroll
    for (int mt = 0; mt < 4; mt++) {
        int mr0 = m0 + mbase + mt*16 + g;
        int mr1 = mr0 + 8;
        int or0 = (mr0 & 255)*NN + (mr0 >> 8);   // swapaxes scatter
        int or1 = (mr1 & 255)*NN + (mr1 >> 8);
        #pragma unroll
        for (int nt = 0; nt < 4; nt++) {
            int col = nbase + nt*8 + 2*t;
            float2 b2 = *(const float2*)&bo[col];
            float2 w0 = make_float2(acc[mt][nt][0] + b2.x, acc[mt][nt][1] + b2.y);
            float2 w1 = make_float2(acc[mt][nt][2] + b2.x, acc[mt][nt][3] + b2.y);
            *(float2*)&out[or0*CC + col] = w0;
            *(float2*)&out[or1*CC + col] = w1;
        }
    }
}

// ---------------------------------------------------------------
extern "C" void kernel_launch(void* const* d_in, const int* in_sizes, int n_in,
                              void* d_out, int out_size)
{
    const float* x      = (const float*)d_in[0];
    const float* mask   = (const float*)d_in[1];
    const float* ln_w   = (const float*)d_in[2];
    const float* ln_b   = (const float*)d_in[3];
    const float* w_bias = (const float*)d_in[4];
    const float* wq     = (const float*)d_in[5];
    const float* wk     = (const float*)d_in[6];
    const float* wv     = (const float*)d_in[7];
    const float* wg     = (const float*)d_in[8];
    const float* bg     = (const float*)d_in[9];
    const float* wo     = (const float*)d_in[10];
    const float* bo     = (const float*)d_in[11];
    float* out = (float*)d_out;

    static bool attr_set = false;
    if (!attr_set) {
        cudaFuncSetAttribute(attn_mma, cudaFuncAttributeMaxDynamicSharedMemorySize,
                             ATTN_SMEM);
        cudaFuncSetAttribute(gemm_proj_tf32, cudaFuncAttributeMaxDynamicSharedMemorySize,
                             PROJ_SMEM);
        cudaFuncSetAttribute(gemm_out_tf32, cudaFuncAttributeMaxDynamicSharedMemorySize,
                             PROJ_SMEM);
        attr_set = true;
    }

    ln_kernel<<<MM/8, 256>>>(x, ln_w, ln_b, w_bias);
    gemm_proj_tf32<<<dim3(MM/128, 4), 256, PROJ_SMEM>>>(wq, wk, wv, wg);
    transpose_wo<<<64, 256>>>(wo);
    attn_mma<<<dim3(NN, HH), 256, ATTN_SMEM>>>(mask);
    gemm_out_tf32<<<dim3(MM/128, 1), 256, PROJ_SMEM>>>(bg, bo, out);
}

// round 11
// speedup vs baseline: 1.9103x; 1.4235x over previous
#include <cuda_runtime.h>
#include <cuda_fp16.h>
#include <math.h>
#include <float.h>
#include <stdint.h>

#define NN 256
#define CC 128
#define HH 4
#define DD 32
#define MM (NN*NN)     // 65536
#define HD (HH*DD)     // 128
#define INF_ 1e9f
#define LN_EPS 1e-5f

// ---- scratch (all half data stored as uint32 half2 words for alignment) ----
__device__ uint32_t g_xn32[MM*CC/2];     // xn half2-packed along C
__device__ uint32_t g_q32 [MM*HD/2];     // q half, scale applied
__device__ uint32_t g_k32 [MM*HD/2];     // k half
__device__ uint32_t g_vt32[MM*HD/2];     // v half, layout [I][h][d][key]
__device__ float    g_g  [MM*HD];        // gate pre-sigmoid (fp32)
__device__ float    g_o  [MM*HD];        // attn out (fp32)
__device__ float    g_tbt[HH*NN*NN];     // [h][j][k]
__device__ uint32_t g_wp32[4*HD*CC/2];   // [wi][n][kp] = half2(W[2kp][n],W[2kp+1][n])
__device__ uint32_t g_wop32[CC*HD/2];    // [n][kp] = half2(wo[n][2kp],wo[n][2kp+1])

// ---------------------------------------------------------------
__device__ __forceinline__ uint32_t pack_h2(float lo, float hi) {
    __half2 h = __floats2half2_rn(lo, hi);
    return *(uint32_t*)&h;
}

__device__ __forceinline__ void mma_f16(float c[4], const uint32_t a[4],
                                        uint32_t b0, uint32_t b1) {
    asm volatile(
        "mma.sync.aligned.m16n8k16.row.col.f32.f16.f16.f32 "
        "{%0,%1,%2,%3}, {%4,%5,%6,%7}, {%8,%9}, {%0,%1,%2,%3};\n"
        : "+f"(c[0]), "+f"(c[1]), "+f"(c[2]), "+f"(c[3])
        : "r"(a[0]), "r"(a[1]), "r"(a[2]), "r"(a[3]), "r"(b0), "r"(b1));
}

// ---------------------------------------------------------------
// Kernel 0: pack weights to half2 (W^T for q/k/v/g, wo rows for out)
// ---------------------------------------------------------------
__global__ void prep_weights(const float* __restrict__ wq, const float* __restrict__ wk,
                             const float* __restrict__ wv, const float* __restrict__ wg,
                             const float* __restrict__ wo)
{
    int idx = blockIdx.x * 256 + threadIdx.x;
    if (idx < 4*HD*CC/2) {
        int wi = idx >> 13;                 // /(128*64)
        int rem = idx & 8191;
        int n = rem >> 6, kp = rem & 63;
        const float* W = (wi == 0) ? wq : (wi == 1) ? wk : (wi == 2) ? wv : wg;
        g_wp32[idx] = pack_h2(W[(2*kp)*HD + n], W[(2*kp + 1)*HD + n]);
    } else {
        int r = idx - 4*HD*CC/2;            // 0..8191
        int n = r >> 6, kp = r & 63;
        g_wop32[r] = pack_h2(wo[n*HD + 2*kp], wo[n*HD + 2*kp + 1]);
    }
}

// ---------------------------------------------------------------
// Kernel 1: LayerNorm (warp per row) + triangle-bias dots
// ---------------------------------------------------------------
__global__ __launch_bounds__(256)
void ln_kernel(const float* __restrict__ x,
               const float* __restrict__ ln_w,
               const float* __restrict__ ln_b,
               const float* __restrict__ w_bias)
{
    int warp = threadIdx.x >> 5, lane = threadIdx.x & 31;
    int m  = blockIdx.x * 8 + warp;
    int i1 = m >> 8;
    int i2 = m & 255;

    float4 v4 = *(const float4*)&x[(i2*NN + i1)*CC + lane*4];

    float s = v4.x + v4.y + v4.z + v4.w;
    #pragma unroll
    for (int o = 16; o > 0; o >>= 1) s += __shfl_xor_sync(0xffffffffu, s, o);
    float mu = s * (1.0f / CC);

    float dx = v4.x - mu, dy = v4.y - mu, dz = v4.z - mu, dw = v4.w - mu;
    float s2 = dx*dx + dy*dy + dz*dz + dw*dw;
    #pragma unroll
    for (int o = 16; o > 0; o >>= 1) s2 += __shfl_xor_sync(0xffffffffu, s2, o);
    float rs = rsqrtf(s2 * (1.0f / CC) + LN_EPS);

    float4 w4 = *(const float4*)&ln_w[lane*4];
    float4 b4 = *(const float4*)&ln_b[lane*4];
    float xn0 = dx*rs*w4.x + b4.x;
    float xn1 = dy*rs*w4.y + b4.y;
    float xn2 = dz*rs*w4.z + b4.z;
    float xn3 = dw*rs*w4.w + b4.w;

    *(uint2*)&g_xn32[m*(CC/2) + lane*2] =
        make_uint2(pack_h2(xn0, xn1), pack_h2(xn2, xn3));

    // triangle bias dots; layout [h][j=i1][k=i2]
    float acc[4];
    #pragma unroll
    for (int h = 0; h < 4; h++) {
        float4 wb = *(const float4*)&w_bias[h*CC + lane*4];
        acc[h] = xn0*wb.x + xn1*wb.y + xn2*wb.z + xn3*wb.w;
    }
    #pragma unroll
    for (int o = 16; o > 0; o >>= 1) {
        #pragma unroll
        for (int h = 0; h < 4; h++)
            acc[h] += __shfl_xor_sync(0xffffffffu, acc[h], o);
    }
    if (lane < 4)
        g_tbt[(lane*NN + i1)*NN + i2] = acc[lane];
}

// ---------------------------------------------------------------
// Kernel 2: q/k/v/g projections, f16 mma m16n8k16.
// grid (512, 4). Single K pass (whole K=128 in smem).
// As[m][kp] stride 68, Bs[n][kp] stride 68 (words).
// ---------------------------------------------------------------
#define TS_STR 68
#define TS_SZ (128*TS_STR)
#define GEMM_SMEM (2*TS_SZ*4)     // 69632 B

__global__ __launch_bounds__(256, 2)
void gemm_proj_f16(const float* __restrict__ bgdummy)
{
    extern __shared__ uint32_t ts[];
    uint32_t* As = ts;
    uint32_t* Bs = ts + TS_SZ;

    int wi = blockIdx.y;
    int m0 = blockIdx.x * 128;
    float osc = (wi == 0) ? 0.17677669529663689f : 1.0f;

    int tid = threadIdx.x;
    int warp = tid >> 5, lane = tid & 31;
    int g = lane >> 2, t = lane & 3;
    int wm = warp >> 2, wn = warp & 3;
    int mbase = wm*64, nbase = wn*32;

    // load A (xn half2) and B (packed W^T) — uint4 copies
    const uint32_t* wp = g_wp32 + wi*HD*(CC/2);
    #pragma unroll
    for (int i = 0; i < 8; i++) {
        int f = tid + 256*i;                // 0..2047
        int r = f >> 4, q4 = (f & 15) * 4;
        *(uint4*)&As[r*TS_STR + q4] = *(const uint4*)&g_xn32[(m0 + r)*(CC/2) + q4];
        *(uint4*)&Bs[r*TS_STR + q4] = *(const uint4*)&wp[r*(CC/2) + q4];
    }
    __syncthreads();

    float acc[4][4][4] = {};

    #pragma unroll
    for (int ks = 0; ks < 8; ks++) {        // K chunks of 16
        uint32_t af[4][4];
        #pragma unroll
        for (int mt = 0; mt < 4; mt++) {
            int r0 = mbase + mt*16 + g;
            af[mt][0] = As[ r0     *TS_STR + ks*8 + t    ];
            af[mt][1] = As[(r0 + 8)*TS_STR + ks*8 + t    ];
            af[mt][2] = As[ r0     *TS_STR + ks*8 + t + 4];
            af[mt][3] = As[(r0 + 8)*TS_STR + ks*8 + t + 4];
        }
        uint32_t bf0[4], bf1[4];
        #pragma unroll
        for (int nt = 0; nt < 4; nt++) {
            int nc = nbase + nt*8 + g;
            bf0[nt] = Bs[nc*TS_STR + ks*8 + t    ];
            bf1[nt] = Bs[nc*TS_STR + ks*8 + t + 4];
        }
        #pragma unroll
        for (int mt = 0; mt < 4; mt++)
            #pragma unroll
            for (int nt = 0; nt < 4; nt++)
                mma_f16(acc[mt][nt], af[mt], bf0[nt], bf1[nt]);
    }

    // epilogue
    #pragma unroll
    for (int mt = 0; mt < 4; mt++) {
        int row0 = m0 + mbase + mt*16 + g;
        int row1 = row0 + 8;
        #pragma unroll
        for (int nt = 0; nt < 4; nt++) {
            int ncol = nbase + nt*8 + 2*t;          // even column
            float c00 = acc[mt][nt][0]*osc, c01 = acc[mt][nt][1]*osc;
            float c10 = acc[mt][nt][2]*osc, c11 = acc[mt][nt][3]*osc;
            if (wi == 0) {
                g_q32[row0*(HD/2) + (ncol >> 1)] = pack_h2(c00, c01);
                g_q32[row1*(HD/2) + (ncol >> 1)] = pack_h2(c10, c11);
            } else if (wi == 1) {
                g_k32[row0*(HD/2) + (ncol >> 1)] = pack_h2(c00, c01);
                g_k32[row1*(HD/2) + (ncol >> 1)] = pack_h2(c10, c11);
            } else if (wi == 2) {
                // transposed scatter: [I][h][d][key]
                __half* vt = (__half*)g_vt32;
                int h = ncol >> 5, d = ncol & 31;
                int I0 = row0 >> 8, key0 = row0 & 255;
                int I1 = row1 >> 8, key1 = row1 & 255;
                vt[((I0*HH + h)*DD + d    )*NN + key0] = __float2half_rn(c00);
                vt[((I0*HH + h)*DD + d + 1)*NN + key0] = __float2half_rn(c01);
                vt[((I1*HH + h)*DD + d    )*NN + key1] = __float2half_rn(c10);
                vt[((I1*HH + h)*DD + d + 1)*NN + key1] = __float2half_rn(c11);
            } else {
                *(float2*)&g_g[row0*HD + ncol] = make_float2(c00, c01);
                *(float2*)&g_g[row1*HD + ncol] = make_float2(c10, c11);
            }
        }
    }
}

// ---------------------------------------------------------------
// Kernel 3: f16 mma flash attention. 8 warps x 32 queries, 32-key chunks.
// Ksh [256 key][20 words] (16 data + 4 pad), Vt [32 d][132 words].
// No-max softmax; P repack via cvt.f16x2 (layout identity, no shuffles).
// ---------------------------------------------------------------
#define KSH_STR 20
#define VT_STR 132
#define ATTN_SMEM ((NN*KSH_STR + DD*VT_STR + NN) * 4)   // 38400 B

__global__ __launch_bounds__(256, 2)
void attn_f16(const float* __restrict__ mask)
{
    extern __shared__ uint32_t sm32[];
    uint32_t* Ksh = sm32;                       // [256][20]
    uint32_t* Vt  = sm32 + NN*KSH_STR;          // [32][132]
    float*    mb  = (float*)(sm32 + NN*KSH_STR + DD*VT_STR); // [256]

    int I = blockIdx.x, h = blockIdx.y;
    int tid  = threadIdx.x;
    int warp = tid >> 5, lane = tid & 31;
    int g = lane >> 2, t = lane & 3;

    // fill K: [key][16 words] from g_k32 rows
    #pragma unroll
    for (int i = 0; i < 16; i++) {
        int idx = tid + 256*i;                  // 0..4095
        int key = idx >> 4, w = idx & 15;
        Ksh[key*KSH_STR + w] = g_k32[(size_t)(I*NN + key)*(HD/2) + h*16 + w];
    }
    // fill Vt: [d][128 words] from g_vt32 (contiguous rows)
    {
        const uint32_t* vsrc = g_vt32 + (size_t)(I*HH + h)*DD*(NN/2);
        #pragma unroll
        for (int i = 0; i < 16; i++) {
            int idx = tid + 256*i;              // 0..4095
            int d = idx >> 7, w = idx & 127;
            Vt[d*VT_STR + w] = vsrc[d*(NN/2) + w];
        }
    }
    mb[tid] = INF_ * (mask[tid*NN + I] - 1.0f);

    // resident Q fragments (half2), scale pre-applied
    int q0 = warp * 32;
    const uint32_t* qbase = g_q32 + (size_t)(I*NN)*(HD/2) + h*16;
    uint32_t aq[2][2][4];
    #pragma unroll
    for (int mt = 0; mt < 2; mt++)
        #pragma unroll
        for (int ks = 0; ks < 2; ks++) {
            int r0 = q0 + mt*16 + g;
            aq[mt][ks][0] = qbase[(size_t) r0     *(HD/2) + ks*8 + t    ];
            aq[mt][ks][1] = qbase[(size_t)(r0 + 8)*(HD/2) + ks*8 + t    ];
            aq[mt][ks][2] = qbase[(size_t) r0     *(HD/2) + ks*8 + t + 4];
            aq[mt][ks][3] = qbase[(size_t)(r0 + 8)*(HD/2) + ks*8 + t + 4];
        }

    float Of[2][4][4] = {};
    float lacc[2][2] = {};

    const float* tbp = g_tbt + h*NN*NN;         // [j][k]

    __syncthreads();

    for (int kc = 0; kc < NN; kc += 32) {
        // ---- S = Q K^T (32 keys, f16 mma k=16 x2) ----
        float S[2][4][4] = {};
        #pragma unroll
        for (int nt = 0; nt < 4; nt++) {
            int krow = (kc + nt*8 + g)*KSH_STR;
            #pragma unroll
            for (int ks = 0; ks < 2; ks++) {
                uint32_t b0 = Ksh[krow + ks*8 + t    ];
                uint32_t b1 = Ksh[krow + ks*8 + t + 4];
                mma_f16(S[0][nt], aq[0][ks], b0, b1);
                mma_f16(S[1][nt], aq[1][ks], b0, b1);
            }
        }
        // ---- biases + exp + row sums ----
        #pragma unroll
        for (int nt = 0; nt < 4; nt++) {
            int kcol = kc + nt*8 + t*2;
            float2 mbv = *(const float2*)&mb[kcol];
            #pragma unroll
            for (int mt = 0; mt < 2; mt++) {
                int row0 = q0 + mt*16 + g;
                float2 t0 = *(const float2*)&tbp[ row0     *NN + kcol];
                float2 t1 = *(const float2*)&tbp[(row0 + 8)*NN + kcol];
                float p0 = __expf(S[mt][nt][0] + mbv.x + t0.x);
                float p1 = __expf(S[mt][nt][1] + mbv.y + t0.y);
                float p2 = __expf(S[mt][nt][2] + mbv.x + t1.x);
                float p3 = __expf(S[mt][nt][3] + mbv.y + t1.y);
                S[mt][nt][0] = p0; S[mt][nt][1] = p1;
                S[mt][nt][2] = p2; S[mt][nt][3] = p3;
                lacc[mt][0] += p0 + p1;
                lacc[mt][1] += p2 + p3;
            }
        }
        // ---- O += P V  (k=16 keys per mma; P layout identity) ----
        #pragma unroll
        for (int kh = 0; kh < 2; kh++) {
            int kcp = (kc >> 1) + kh*8;         // keypair word offset
            uint32_t bv0[4], bv1[4];
            #pragma unroll
            for (int ntd = 0; ntd < 4; ntd++) {
                int vrow = (ntd*8 + g)*VT_STR;
                bv0[ntd] = Vt[vrow + kcp + t    ];
                bv1[ntd] = Vt[vrow + kcp + t + 4];
            }
            #pragma unroll
            for (int mt = 0; mt < 2; mt++) {
                uint32_t ap[4];
                ap[0] = pack_h2(S[mt][kh*2  ][0], S[mt][kh*2  ][1]);
                ap[1] = pack_h2(S[mt][kh*2  ][2], S[mt][kh*2  ][3]);
                ap[2] = pack_h2(S[mt][kh*2+1][0], S[mt][kh*2+1][1]);
                ap[3] = pack_h2(S[mt][kh*2+1][2], S[mt][kh*2+1][3]);
                #pragma unroll
                for (int ntd = 0; ntd < 4; ntd++)
                    mma_f16(Of[mt][ntd], ap, bv0[ntd], bv1[ntd]);
            }
        }
    }

    // ---- epilogue ----
    float* obase = g_o + (size_t)(I*NN)*HD + h*DD;
    #pragma unroll
    for (int mt = 0; mt < 2; mt++) {
        float l0 = lacc[mt][0];
        l0 += __shfl_xor_sync(0xffffffffu, l0, 1);
        l0 += __shfl_xor_sync(0xffffffffu, l0, 2);
        float l1 = lacc[mt][1];
        l1 += __shfl_xor_sync(0xffffffffu, l1, 1);
        l1 += __shfl_xor_sync(0xffffffffu, l1, 2);
        float inv0 = 1.0f / l0;
        float inv1 = 1.0f / l1;
        int row0 = q0 + mt*16 + g;
        int row1 = row0 + 8;
        #pragma unroll
        for (int ntd = 0; ntd < 4; ntd++) {
            int col = ntd*8 + t*2;
            float2 w0 = make_float2(Of[mt][ntd][0]*inv0, Of[mt][ntd][1]*inv0);
            float2 w1 = make_float2(Of[mt][ntd][2]*inv1, Of[mt][ntd][3]*inv1);
            *(float2*)&obase[row0*HD + col] = w0;
            *(float2*)&obase[row1*HD + col] = w1;
        }
    }
}

// ---------------------------------------------------------------
// Kernel 4: gated output projection, f16 mma + scatter epilogue
// ---------------------------------------------------------------
__global__ __launch_bounds__(256, 2)
void gemm_out_f16(const float* __restrict__ bg, const float* __restrict__ bo,
                  float* __restrict__ out)
{
    extern __shared__ uint32_t ts[];
    uint32_t* As = ts;
    uint32_t* Bs = ts + TS_SZ;

    int m0 = blockIdx.x * 128;

    int tid = threadIdx.x;
    int warp = tid >> 5, lane = tid & 31;
    int g = lane >> 2, t = lane & 3;
    int wm = warp >> 2, wn = warp & 3;
    int mbase = wm*64, nbase = wn*32;

    // A: gate+pack; B: copy packed wo
    #pragma unroll
    for (int i = 0; i < 16; i++) {
        int idx = tid + 256*i;                  // 0..4095
        int r = idx >> 5, q = idx & 31;         // q -> 4 k's
        int k0 = q*4;
        float4 o4  = *(const float4*)&g_o[(m0 + r)*HD + k0];
        float4 g4  = *(const float4*)&g_g[(m0 + r)*HD + k0];
        float4 bg4 = *(const float4*)&bg[k0];
        float a0 = o4.x / (1.0f + __expf(-(g4.x + bg4.x)));
        float a1 = o4.y / (1.0f + __expf(-(g4.y + bg4.y)));
        float a2 = o4.z / (1.0f + __expf(-(g4.z + bg4.z)));
        float a3 = o4.w / (1.0f + __expf(-(g4.w + bg4.w)));
        As[r*TS_STR + k0/2    ] = pack_h2(a0, a1);
        As[r*TS_STR + k0/2 + 1] = pack_h2(a2, a3);
    }
    #pragma unroll
    for (int i = 0; i < 8; i++) {
        int f = tid + 256*i;                    // 0..2047
        int n = f >> 4, kp4 = (f & 15) * 4;
        *(uint4*)&Bs[n*TS_STR + kp4] = *(const uint4*)&g_wop32[n*(HD/2) + kp4];
    }
    __syncthreads();

    float acc[4][4][4] = {};

    #pragma unroll
    for (int ks = 0; ks < 8; ks++) {
        uint32_t af[4][4];
        #pragma unroll
        for (int mt = 0; mt < 4; mt++) {
            int r0 = mbase + mt*16 + g;
            af[mt][0] = As[ r0     *TS_STR + ks*8 + t    ];
            af[mt][1] = As[(r0 + 8)*TS_STR + ks*8 + t    ];
            af[mt][2] = As[ r0     *TS_STR + ks*8 + t + 4];
            af[mt][3] = As[(r0 + 8)*TS_STR + ks*8 + t + 4];
        }
        uint32_t bf0[4], bf1[4];
        #pragma unroll
        for (int nt = 0; nt < 4; nt++) {
            int nc = nbase + nt*8 + g;
            bf0[nt] = Bs[nc*TS_STR + ks*8 + t    ];
            bf1[nt] = Bs[nc*TS_STR + ks*8 + t + 4];
        }
        #pragma unroll
        for (int mt = 0; mt < 4; mt++)
            #pragma unroll
            for (int nt = 0; nt < 4; nt++)
                mma_f16(acc[mt][nt], af[mt], bf0[nt], bf1[nt]);
    }

    #pragma unroll
    for (int mt = 0; mt < 4; mt++) {
        int mr0 = m0 + mbase + mt*16 + g;
        int mr1 = mr0 + 8;
        int or0 = (mr0 & 255)*NN + (mr0 >> 8);   // swapaxes scatter
        int or1 = (mr1 & 255)*NN + (mr1 >> 8);
        #pragma unroll
        for (int nt = 0; nt < 4; nt++) {
            int col = nbase + nt*8 + 2*t;
            float2 b2 = *(const float2*)&bo[col];
            float2 w0 = make_float2(acc[mt][nt][0] + b2.x, acc[mt][nt][1] + b2.y);
            float2 w1 = make_float2(acc[mt][nt][2] + b2.x, acc[mt][nt][3] + b2.y);
            *(float2*)&out[or0*CC + col] = w0;
            *(float2*)&out[or1*CC + col] = w1;
        }
    }
}

// ---------------------------------------------------------------
extern "C" void kernel_launch(void* const* d_in, const int* in_sizes, int n_in,
                              void* d_out, int out_size)
{
    const float* x      = (const float*)d_in[0];
    const float* mask   = (const float*)d_in[1];
    const float* ln_w   = (const float*)d_in[2];
    const float* ln_b   = (const float*)d_in[3];
    const float* w_bias = (const float*)d_in[4];
    const float* wq     = (const float*)d_in[5];
    const float* wk     = (const float*)d_in[6];
    const float* wv     = (const float*)d_in[7];
    const float* wg     = (const float*)d_in[8];
    const float* bg     = (const float*)d_in[9];
    const float* wo     = (const float*)d_in[10];
    const float* bo     = (const float*)d_in[11];
    float* out = (float*)d_out;

    static bool attr_set = false;
    if (!attr_set) {
        cudaFuncSetAttribute(attn_f16, cudaFuncAttributeMaxDynamicSharedMemorySize,
                             ATTN_SMEM);
        cudaFuncSetAttribute(gemm_proj_f16, cudaFuncAttributeMaxDynamicSharedMemorySize,
                             GEMM_SMEM);
        cudaFuncSetAttribute(gemm_out_f16, cudaFuncAttributeMaxDynamicSharedMemorySize,
                             GEMM_SMEM);
        attr_set = true;
    }

    prep_weights<<<160, 256>>>(wq, wk, wv, wg, wo);
    ln_kernel<<<MM/8, 256>>>(x, ln_w, ln_b, w_bias);
    gemm_proj_f16<<<dim3(MM/128, 4), 256, GEMM_SMEM>>>(nullptr);
    attn_f16<<<dim3(NN, HH), 256, ATTN_SMEM>>>(mask);
    gemm_out_f16<<<dim3(MM/128, 1), 256, GEMM_SMEM>>>(bg, bo, out);
}